// round 1
// baseline (speedup 1.0000x reference)
#include <cuda_runtime.h>

// Problem constants (from reference)
#define BATCH    32
#define CH       2048
#define SZ       4096
#define CSPLIT   8                  // c-dimension splits (partial-sum stage)
#define CCHUNK   (CH / CSPLIT)      // 256 c iterations per block
#define BG       4                  // batches per block (w reuse factor)
#define TPB      128                // threads per block
#define S_PER_BLOCK (TPB * 4)       // 512 s-columns per block (float4/thread)

// 8 * 32 * 4096 floats = 4 MB partial-sum scratch (allocation-free rule)
__device__ float g_partial[CSPLIT * BATCH * SZ];

__global__ __launch_bounds__(TPB) void CWG_partial_kernel(
    const float* __restrict__ x,
    const float* __restrict__ w)
{
    const int s0  = blockIdx.x * S_PER_BLOCK + threadIdx.x * 4;
    const int b0  = blockIdx.y * BG;
    const int cs  = blockIdx.z;
    const int c0  = cs * CCHUNK;

    float4 acc[BG];
#pragma unroll
    for (int b = 0; b < BG; b++) acc[b] = make_float4(0.f, 0.f, 0.f, 0.f);

    const float* wp = w + (size_t)c0 * SZ + s0;
    const float* xp = x + ((size_t)b0 * CH + (size_t)c0) * SZ + s0;

#pragma unroll 4
    for (int c = 0; c < CCHUNK; c++) {
        const float4 wv = __ldg((const float4*)(wp + (size_t)c * SZ));
#pragma unroll
        for (int b = 0; b < BG; b++) {
            const float4 xv = __ldg((const float4*)(xp + ((size_t)b * CH + (size_t)c) * SZ));
            acc[b].x = fmaf(xv.x, wv.x, acc[b].x);
            acc[b].y = fmaf(xv.y, wv.y, acc[b].y);
            acc[b].z = fmaf(xv.z, wv.z, acc[b].z);
            acc[b].w = fmaf(xv.w, wv.w, acc[b].w);
        }
    }

#pragma unroll
    for (int b = 0; b < BG; b++) {
        *(float4*)(g_partial + ((size_t)cs * BATCH + (size_t)(b0 + b)) * SZ + s0) = acc[b];
    }
}

__global__ __launch_bounds__(256) void CWG_finalize_kernel(
    const float* __restrict__ bias,
    float* __restrict__ out)
{
    const int i = blockIdx.x * 256 + threadIdx.x;   // over BATCH*SZ = 131072
    if (i >= BATCH * SZ) return;
    const int s = i & (SZ - 1);

    float sum = 0.f;
#pragma unroll
    for (int k = 0; k < CSPLIT; k++)
        sum += g_partial[(size_t)k * BATCH * SZ + i];

    sum += bias[s];
    out[i] = fmaxf(sum, 0.f);
}

extern "C" void kernel_launch(void* const* d_in, const int* in_sizes, int n_in,
                              void* d_out, int out_size)
{
    const float* x    = (const float*)d_in[0];
    const float* w    = (const float*)d_in[1];
    const float* bias = (const float*)d_in[2];
    float* out        = (float*)d_out;

    dim3 grid(SZ / S_PER_BLOCK, BATCH / BG, CSPLIT);  // (8, 8, 8) = 512 blocks
    CWG_partial_kernel<<<grid, TPB>>>(x, w);

    CWG_finalize_kernel<<<(BATCH * SZ + 255) / 256, 256>>>(bias, out);
}

// round 2
// speedup vs baseline: 1.2135x; 1.2135x over previous
#include <cuda_runtime.h>

// Problem constants
#define BATCH    32
#define CH       2048
#define SZ       4096
#define CSPLIT   16                 // c-dimension splits (finer tiles -> smaller tail)
#define CCHUNK   (CH / CSPLIT)      // 128 c iterations per block
#define BG       4                  // batches per block (w reuse factor)
#define TPB      128                // threads per block
#define S_PER_BLOCK (TPB * 4)       // 512 s-columns per block (float4/thread)

// 16 * 32 * 4096 floats = 8 MB partial-sum scratch
__device__ float g_partial[CSPLIT * BATCH * SZ];

// Streaming load (evict-first): don't let 1 GiB of x thrash w out of L2
__device__ __forceinline__ float4 ldcs4(const float* p) {
    float4 v;
    asm volatile("ld.global.cs.v4.f32 {%0,%1,%2,%3}, [%4];"
                 : "=f"(v.x), "=f"(v.y), "=f"(v.z), "=f"(v.w) : "l"(p));
    return v;
}

__global__ __launch_bounds__(TPB) void CWG_partial_kernel(
    const float* __restrict__ x,
    const float* __restrict__ w)
{
    const int s0  = blockIdx.x * S_PER_BLOCK + threadIdx.x * 4;
    const int b0  = blockIdx.y * BG;
    const int cs  = blockIdx.z;
    const int c0  = cs * CCHUNK;

    float4 acc[BG];
#pragma unroll
    for (int b = 0; b < BG; b++) acc[b] = make_float4(0.f, 0.f, 0.f, 0.f);

    const float* wp = w + (size_t)c0 * SZ + s0;
    const float* xp = x + ((size_t)b0 * CH + (size_t)c0) * SZ + s0;

#pragma unroll 4
    for (int c = 0; c < CCHUNK; c++) {
        const float4 wv = __ldg((const float4*)(wp + (size_t)c * SZ));
#pragma unroll
        for (int b = 0; b < BG; b++) {
            const float4 xv = ldcs4(xp + ((size_t)b * CH + (size_t)c) * SZ);
            acc[b].x = fmaf(xv.x, wv.x, acc[b].x);
            acc[b].y = fmaf(xv.y, wv.y, acc[b].y);
            acc[b].z = fmaf(xv.z, wv.z, acc[b].z);
            acc[b].w = fmaf(xv.w, wv.w, acc[b].w);
        }
    }

#pragma unroll
    for (int b = 0; b < BG; b++) {
        // streaming store: partials are consumed once by finalize
        const float4 v = acc[b];
        float* dst = g_partial + ((size_t)cs * BATCH + (size_t)(b0 + b)) * SZ + s0;
        asm volatile("st.global.cs.v4.f32 [%0], {%1,%2,%3,%4};"
                     :: "l"(dst), "f"(v.x), "f"(v.y), "f"(v.z), "f"(v.w));
    }
}

__global__ __launch_bounds__(256) void CWG_finalize_kernel(
    const float* __restrict__ bias,
    float* __restrict__ out)
{
    // float4 per thread: 32768 threads cover BATCH*SZ = 131072 floats
    const int i4 = blockIdx.x * 256 + threadIdx.x;       // float4 index
    const int i  = i4 * 4;
    const int s  = i & (SZ - 1);

    float4 sum = make_float4(0.f, 0.f, 0.f, 0.f);
#pragma unroll
    for (int k = 0; k < CSPLIT; k++) {
        const float4 p = ldcs4(g_partial + (size_t)k * BATCH * SZ + i);
        sum.x += p.x; sum.y += p.y; sum.z += p.z; sum.w += p.w;
    }

    const float4 bv = *(const float4*)(bias + s);
    float4 r;
    r.x = fmaxf(sum.x + bv.x, 0.f);
    r.y = fmaxf(sum.y + bv.y, 0.f);
    r.z = fmaxf(sum.z + bv.z, 0.f);
    r.w = fmaxf(sum.w + bv.w, 0.f);
    *(float4*)(out + i) = r;
}

extern "C" void kernel_launch(void* const* d_in, const int* in_sizes, int n_in,
                              void* d_out, int out_size)
{
    const float* x    = (const float*)d_in[0];
    const float* w    = (const float*)d_in[1];
    const float* bias = (const float*)d_in[2];
    float* out        = (float*)d_out;

    dim3 grid(SZ / S_PER_BLOCK, BATCH / BG, CSPLIT);  // (8, 8, 16) = 1024 blocks
    CWG_partial_kernel<<<grid, TPB>>>(x, w);

    CWG_finalize_kernel<<<(BATCH * SZ / 4) / 256, 256>>>(bias, out);
}